// round 17
// baseline (speedup 1.0000x reference)
#include <cuda_runtime.h>
#include <cuda_bf16.h>
#include <cuda_fp16.h>
#include <cstdint>

// Problem constants (fixed by the dataset)
#define MAXN 101024
#define MAXE 2000000
#define FEAT 1024
#define H0 128

// ---------------- scratch (device globals; no allocation allowed) ----------
__device__ __half g_h16[(size_t)(MAXN + 128) * H0];  // proj output, fp16 (padded)
__device__ __half g_hw16a[(size_t)MAXN * H0];        // hw table A
__device__ __half g_hw16b[(size_t)MAXN * H0];        // hw table B
__device__ float g_dinv[MAXN];
__device__ int   g_cnt[MAXN];
__device__ int   g_rowoff[MAXN + 1];
__device__ int   g_cursor[MAXN];
__device__ int   g_rowtmp[MAXN];
__device__ int   g_bsum[128];
__device__ int   g_boff[128];
__device__ int   g_esrc[MAXE];
__device__ float g_enorm[MAXE];

// fp16 weight buffers, transposed to B-format [n][k]
__device__ __half g_bh_u[128 * 1024];
__device__ __half g_bh_b[128 * 1024];
__device__ __half g_bh_1[128 * 128];
__device__ __half g_bh_2[128 * 128];
__device__ __half g_bh_3[64 * 128];

// ---------------- CSR construction ----------------------------------------
__global__ void zero_cnt_kernel(int n) {
    int i = blockIdx.x * blockDim.x + threadIdx.x;
    if (i < n) g_cnt[i] = 0;
}

__global__ void count_kernel(const int* __restrict__ dst, int E) {
    int i = blockIdx.x * blockDim.x + threadIdx.x;
    if (i < E) atomicAdd(&g_cnt[dst[i]], 1);
}

__global__ void dinv_kernel(int n) {
    int i = blockIdx.x * blockDim.x + threadIdx.x;
    if (i < n) g_dinv[i] = rsqrtf((float)(g_cnt[i] + 1));  // +1 self loop
}

__global__ void scan_block_kernel(int n) {
    __shared__ int sh[1024];
    int tid = threadIdx.x;
    int i = blockIdx.x * 1024 + tid;
    int v = (i < n) ? g_cnt[i] : 0;
    sh[tid] = v;
    __syncthreads();
    for (int off = 1; off < 1024; off <<= 1) {
        int t = (tid >= off) ? sh[tid - off] : 0;
        __syncthreads();
        sh[tid] += t;
        __syncthreads();
    }
    if (i < n) g_rowtmp[i] = sh[tid] - v;
    if (tid == 1023) g_bsum[blockIdx.x] = sh[1023];
}

__global__ void scan_bsum_kernel(int nb, int n) {
    __shared__ int sh[128];
    int tid = threadIdx.x;
    int v = (tid < nb) ? g_bsum[tid] : 0;
    sh[tid] = v;
    __syncthreads();
    for (int off = 1; off < 128; off <<= 1) {
        int t = (tid >= off) ? sh[tid - off] : 0;
        __syncthreads();
        sh[tid] += t;
        __syncthreads();
    }
    if (tid < nb) g_boff[tid] = sh[tid] - v;
    if (tid == 127) g_rowoff[n] = sh[127];
}

__global__ void scan_add_kernel(int n) {
    int i = blockIdx.x * blockDim.x + threadIdx.x;
    if (i >= n) return;
    int val = g_rowtmp[i] + g_boff[i >> 10];
    g_rowoff[i] = val;
    g_cursor[i] = val;
}

__global__ void fill_kernel(const int* __restrict__ src, const int* __restrict__ dst, int E) {
    int i = blockIdx.x * blockDim.x + threadIdx.x;
    if (i >= E) return;
    int s = src[i], d = dst[i];
    int p = atomicAdd(&g_cursor[d], 1);
    g_esrc[p]  = s;
    g_enorm[p] = g_dinv[s] * g_dinv[d];
}

// -------- fused weight convert: all 5 weights -> B-format [n][k] fp16 -------
__global__ void convw_all_kernel(const float* __restrict__ Wu, const float* __restrict__ Wb,
                                 const float* __restrict__ W1, const float* __restrict__ W2,
                                 const float* __restrict__ W3,
                                 __half* __restrict__ ou, __half* __restrict__ ob,
                                 __half* __restrict__ o1, __half* __restrict__ o2,
                                 __half* __restrict__ o3)
{
    int idx = blockIdx.x * 256 + threadIdx.x;
    const float* W; __half* B; int K, NC, off;
    if      (idx < 131072) { W = Wu; B = ou; K = 1024; NC = 128; off = 0; }
    else if (idx < 262144) { W = Wb; B = ob; K = 1024; NC = 128; off = 131072; }
    else if (idx < 278528) { W = W1; B = o1; K = 128;  NC = 128; off = 262144; }
    else if (idx < 294912) { W = W2; B = o2; K = 128;  NC = 128; off = 278528; }
    else if (idx < 303104) { W = W3; B = o3; K = 128;  NC = 64;  off = 294912; }
    else return;
    int j = idx - off;
    int k = j / NC, n = j % NC;
    B[n * K + k] = __float2half_rn(W[j]);
}

// ---------------- common mma / cp helpers -----------------------------------
__device__ __forceinline__ void mma16816(float* c, const uint32_t* a, const uint32_t* b) {
    asm volatile(
        "mma.sync.aligned.m16n8k16.row.col.f32.f16.f16.f32 "
        "{%0,%1,%2,%3}, {%4,%5,%6,%7}, {%8,%9}, {%0,%1,%2,%3};\n"
        : "+f"(c[0]), "+f"(c[1]), "+f"(c[2]), "+f"(c[3])
        : "r"(a[0]), "r"(a[1]), "r"(a[2]), "r"(a[3]), "r"(b[0]), "r"(b[1]));
}
__device__ __forceinline__ void cvt_f4_h(float4 v, uint2& hi) {
    __half2 h0 = __floats2half2_rn(v.x, v.y);
    __half2 h1 = __floats2half2_rn(v.z, v.w);
    hi = make_uint2(*(uint32_t*)&h0, *(uint32_t*)&h1);
}
__device__ __forceinline__ void cp_async16(uint32_t saddr, const void* g) {
    asm volatile("cp.async.cg.shared.global [%0], [%1], 16;" :: "r"(saddr), "l"(g));
}
#define CP_COMMIT() asm volatile("cp.async.commit_group;" ::: "memory")
#define CP_WAIT0()  asm volatile("cp.async.wait_group 0;" ::: "memory")

// ---------------- projection GEMM: fp32 A -> fp16 convert, fp16 out ---------
__global__ void __launch_bounds__(256, 2) gemm_proj_kernel(
    const float* __restrict__ A,
    const __half* __restrict__ Bh0, const __half* __restrict__ Bh1,
    const float* __restrict__ bias0, const float* __restrict__ bias1,
    __half* __restrict__ C16, int nrows, int KTOT, int userRows)
{
    constexpr int NCOL = 128;
    constexpr int STR = 40;
    constexpr int WN  = 64, NF = 8;
    constexpr int ASZ = 128 * STR;
    constexpr int BSZ = NCOL * STR;

    extern __shared__ uint16_t sm[];
    uint16_t* As = sm;
    uint16_t* Bs = sm + 2 * ASZ;

    const int tid  = threadIdx.x;
    const int wid  = tid >> 5;
    const int lane = tid & 31;
    const int wm   = wid & 3;
    const int wn   = wid >> 2;
    const int g    = lane >> 2;
    const int t    = lane & 3;

    const int r0   = blockIdx.x * 128;
    const bool set0 = (r0 < userRows);
    const __half* Bh = set0 ? Bh0 : Bh1;
    const float* bias = set0 ? bias0 : bias1;

    float acc[2][NF][4];
#pragma unroll
    for (int mf = 0; mf < 2; mf++)
#pragma unroll
        for (int nf = 0; nf < NF; nf++)
#pragma unroll
            for (int i = 0; i < 4; i++) acc[mf][nf][i] = 0.f;

    const int arow[4] = { (tid + 0*256) >> 3, (tid + 1*256) >> 3,
                          (tid + 2*256) >> 3, (tid + 3*256) >> 3 };
    const int ac4 = (tid & 7) << 2;
    float4 areg[4];

    const int nchunk = KTOT >> 5;

    auto loadA = [&](int c) {
        const int k0 = c << 5;
#pragma unroll
        for (int i = 0; i < 4; i++) {
            int row = arow[i];
            if (r0 + row < nrows)
                areg[i] = *(const float4*)(A + (size_t)(r0 + row) * KTOT + k0 + ac4);
            else
                areg[i] = make_float4(0.f, 0.f, 0.f, 0.f);
        }
    };
    auto storeA = [&](int buf) {
        uint16_t* a_s = As + buf * ASZ;
#pragma unroll
        for (int i = 0; i < 4; i++) {
            uint2 hi;
            cvt_f4_h(areg[i], hi);
            *(uint2*)&a_s[arow[i] * STR + ac4] = hi;
        }
    };
    auto cpB = [&](int c, int buf) {
        const int k0 = c << 5;
        uint16_t* b_s = Bs + buf * BSZ;
#pragma unroll
        for (int i = 0; i < 2; i++) {
            int idx = tid + i * 256;
            int n  = idx >> 2;
            int c8 = (idx & 3) << 3;
            uint32_t sh = (uint32_t)__cvta_generic_to_shared(&b_s[n * STR + c8]);
            cp_async16(sh, Bh + (size_t)n * KTOT + k0 + c8);
        }
        CP_COMMIT();
    };
    auto compute = [&](int buf) {
        uint16_t* a_s = As + buf * ASZ;
        uint16_t* b_s = Bs + buf * BSZ;
#pragma unroll
        for (int ks = 0; ks < 2; ks++) {
            uint32_t ah[2][4];
#pragma unroll
            for (int mf = 0; mf < 2; mf++) {
                int rb = (wm * 32 + mf * 16 + g) * STR + ks * 16 + t * 2;
                int r8 = rb + 8 * STR;
                ah[mf][0] = *(const uint32_t*)&a_s[rb];
                ah[mf][1] = *(const uint32_t*)&a_s[r8];
                ah[mf][2] = *(const uint32_t*)&a_s[rb + 8];
                ah[mf][3] = *(const uint32_t*)&a_s[r8 + 8];
            }
#pragma unroll
            for (int nf = 0; nf < NF; nf++) {
                int bb = (wn * WN + nf * 8 + g) * STR + ks * 16 + t * 2;
                uint32_t bh[2];
                bh[0] = *(const uint32_t*)&b_s[bb];
                bh[1] = *(const uint32_t*)&b_s[bb + 8];
#pragma unroll
                for (int mf = 0; mf < 2; mf++)
                    mma16816(acc[mf][nf], ah[mf], bh);
            }
        }
    };

    loadA(0);
    cpB(0, 0);
    storeA(0);
    CP_WAIT0();
    __syncthreads();

    for (int c = 0; c < nchunk; c++) {
        const int cur = c & 1, nxt = cur ^ 1;
        const bool more = (c + 1 < nchunk);
        if (more) {
            loadA(c + 1);
            cpB(c + 1, nxt);
        }
        compute(cur);
        __syncthreads();
        if (more) {
            storeA(nxt);
            CP_WAIT0();
            __syncthreads();
        }
    }

#pragma unroll
    for (int mf = 0; mf < 2; mf++) {
        int row = r0 + wm * 32 + mf * 16 + g;
#pragma unroll
        for (int nf = 0; nf < NF; nf++) {
            int col = wn * WN + nf * 8 + t * 2;
            float bx = bias[col], by = bias[col + 1];
            if (row < nrows) {
                float2 v = { acc[mf][nf][0] + bx, acc[mf][nf][1] + by };
                *(__half2*)(C16 + (size_t)row * NCOL + col) = __float22half2_rn(v);
            }
            if (row + 8 < nrows) {
                float2 v = { acc[mf][nf][2] + bx, acc[mf][nf][3] + by };
                *(__half2*)(C16 + (size_t)(row + 8) * NCOL + col) = __float22half2_rn(v);
            }
        }
    }
}

// ---------------- layer-1 GEMM: fp16 A (cp.async), fp16 out -----------------
__global__ void __launch_bounds__(256, 2) gemm_h16_kernel(
    const __half* __restrict__ A, const __half* __restrict__ Bh,
    __half* __restrict__ C16, int nrows, int KTOT)
{
    constexpr int NCOL = 128;
    constexpr int STR = 40;
    constexpr int WN  = 64, NF = 8;
    constexpr int ASZ = 128 * STR;
    constexpr int BSZ = NCOL * STR;

    extern __shared__ uint16_t sm[];
    uint16_t* As = sm;
    uint16_t* Bs = sm + 2 * ASZ;

    const int tid  = threadIdx.x;
    const int wid  = tid >> 5;
    const int lane = tid & 31;
    const int wm   = wid & 3;
    const int wn   = wid >> 2;
    const int g    = lane >> 2;
    const int t    = lane & 3;
    const int r0   = blockIdx.x * 128;

    float acc[2][NF][4];
#pragma unroll
    for (int mf = 0; mf < 2; mf++)
#pragma unroll
        for (int nf = 0; nf < NF; nf++)
#pragma unroll
            for (int i = 0; i < 4; i++) acc[mf][nf][i] = 0.f;

    const int nchunk = KTOT >> 5;

    auto cpAB = [&](int c, int buf) {
        const int k0 = c << 5;
        uint16_t* a_s = As + buf * ASZ;
#pragma unroll
        for (int i = 0; i < 2; i++) {
            int idx = tid + i * 256;
            int r  = idx >> 2;
            int c8 = (idx & 3) << 3;
            uint32_t sa = (uint32_t)__cvta_generic_to_shared(&a_s[r * STR + c8]);
            cp_async16(sa, A + (size_t)(r0 + r) * KTOT + k0 + c8);
        }
        uint16_t* b_s = Bs + buf * BSZ;
#pragma unroll
        for (int i = 0; i < 2; i++) {
            int idx = tid + i * 256;
            int n  = idx >> 2;
            int c8 = (idx & 3) << 3;
            uint32_t sb = (uint32_t)__cvta_generic_to_shared(&b_s[n * STR + c8]);
            cp_async16(sb, Bh + (size_t)n * KTOT + k0 + c8);
        }
        CP_COMMIT();
    };
    auto compute = [&](int buf) {
        uint16_t* a_s = As + buf * ASZ;
        uint16_t* b_s = Bs + buf * BSZ;
#pragma unroll
        for (int ks = 0; ks < 2; ks++) {
            uint32_t ah[2][4];
#pragma unroll
            for (int mf = 0; mf < 2; mf++) {
                int rb = (wm * 32 + mf * 16 + g) * STR + ks * 16 + t * 2;
                int r8 = rb + 8 * STR;
                ah[mf][0] = *(const uint32_t*)&a_s[rb];
                ah[mf][1] = *(const uint32_t*)&a_s[r8];
                ah[mf][2] = *(const uint32_t*)&a_s[rb + 8];
                ah[mf][3] = *(const uint32_t*)&a_s[r8 + 8];
            }
#pragma unroll
            for (int nf = 0; nf < NF; nf++) {
                int bb = (wn * WN + nf * 8 + g) * STR + ks * 16 + t * 2;
                uint32_t bh[2];
                bh[0] = *(const uint32_t*)&b_s[bb];
                bh[1] = *(const uint32_t*)&b_s[bb + 8];
#pragma unroll
                for (int mf = 0; mf < 2; mf++)
                    mma16816(acc[mf][nf], ah[mf], bh);
            }
        }
    };

    cpAB(0, 0);
    CP_WAIT0();
    __syncthreads();

    for (int c = 0; c < nchunk; c++) {
        const int cur = c & 1, nxt = cur ^ 1;
        const bool more = (c + 1 < nchunk);
        if (more) cpAB(c + 1, nxt);
        compute(cur);
        if (more) CP_WAIT0();
        __syncthreads();
    }

#pragma unroll
    for (int mf = 0; mf < 2; mf++) {
        int row = r0 + wm * 32 + mf * 16 + g;
#pragma unroll
        for (int nf = 0; nf < NF; nf++) {
            int col = wn * WN + nf * 8 + t * 2;
            if (row < nrows) {
                float2 v = { acc[mf][nf][0], acc[mf][nf][1] };
                *(__half2*)(C16 + (size_t)row * NCOL + col) = __float22half2_rn(v);
            }
            if (row + 8 < nrows) {
                float2 v = { acc[mf][nf][2], acc[mf][nf][3] };
                *(__half2*)(C16 + (size_t)(row + 8) * NCOL + col) = __float22half2_rn(v);
            }
        }
    }
}

// ---------------- fused aggregate + GEMM ------------------------------------
// For tile rows r0..r0+127:
//   phase 0: cp.async whole B ([NCOL][128] in 4 k-chunks)
//   phase 1: warp-per-row aggregate from hwin (self + neighbors, bias, relu)
//            -> fp16 A tile in smem (4 k-chunk layout)
//   phase 2: MMA over 4 chunks -> hwout fp16
template <int NCOL>
__global__ void __launch_bounds__(256, 2) fused_agg_gemm_kernel(
    const __half* __restrict__ hwin,   // [N, 128] previous hw table
    const float* __restrict__ bias,    // previous layer bias (pre-relu)
    const __half* __restrict__ Bh,     // [NCOL][128]
    __half* __restrict__ hwout,        // [N, NCOL]
    int nrows)
{
    constexpr int STR = 40;
    constexpr int WN  = NCOL / 2;
    constexpr int NF  = WN / 8;
    constexpr int ACH = 128 * STR;     // halves per A chunk
    constexpr int BCH = NCOL * STR;    // halves per B chunk

    extern __shared__ uint16_t sm[];
    uint16_t* As = sm;                 // [4][128][STR]
    uint16_t* Bs = sm + 4 * ACH;       // [4][NCOL][STR]

    const int tid  = threadIdx.x;
    const int wid  = tid >> 5;
    const int lane = tid & 31;
    const int wm   = wid & 3;
    const int wn   = wid >> 2;
    const int g    = lane >> 2;
    const int t    = lane & 3;
    const int r0   = blockIdx.x * 128;

    // ---- phase 0: async-load all of B ----
    {
        constexpr int TOT = 16 * NCOL;     // 16B transfers total (4 chunks * NCOL * 4)
#pragma unroll
        for (int i = 0; i < TOT / 256; i++) {
            int idx = tid + i * 256;
            int ch  = idx / (NCOL * 4);
            int rem = idx % (NCOL * 4);
            int n   = rem >> 2;
            int c8  = (rem & 3) << 3;
            uint32_t sb = (uint32_t)__cvta_generic_to_shared(&Bs[ch * BCH + n * STR + c8]);
            cp_async16(sb, Bh + (size_t)n * 128 + ch * 32 + c8);
        }
        CP_COMMIT();
    }

    // ---- phase 1: aggregate 16 rows per warp into smem A ----
    for (int i = 0; i < 16; i++) {
        int lrow = wid * 16 + i;
        int grow = r0 + lrow;
        float a0 = 0.f, a1 = 0.f, a2 = 0.f, a3 = 0.f;
        if (grow < nrows) {
            float di = g_dinv[grow];
            float sl = di * di;
            int2 raw = *(const int2*)(hwin + (size_t)grow * 128 + lane * 4);
            float2 f0 = __half22float2(*(__half2*)&raw.x);
            float2 f1 = __half22float2(*(__half2*)&raw.y);
            a0 = f0.x * sl; a1 = f0.y * sl; a2 = f1.x * sl; a3 = f1.y * sl;

            int e = g_rowoff[grow], end = g_rowoff[grow + 1];
            for (; e + 8 <= end; e += 8) {
                int   s[8];
                float nm[8];
#pragma unroll
                for (int j = 0; j < 8; j++) {
                    s[j]  = __ldg(&g_esrc[e + j]);
                    nm[j] = __ldg(&g_enorm[e + j]);
                }
                int2 r[8];
#pragma unroll
                for (int j = 0; j < 8; j++)
                    r[j] = *(const int2*)(hwin + (size_t)s[j] * 128 + lane * 4);
#pragma unroll
                for (int j = 0; j < 8; j++) {
                    float2 x0 = __half22float2(*(__half2*)&r[j].x);
                    float2 x1 = __half22float2(*(__half2*)&r[j].y);
                    a0 += x0.x * nm[j]; a1 += x0.y * nm[j];
                    a2 += x1.x * nm[j]; a3 += x1.y * nm[j];
                }
            }
            for (; e < end; e++) {
                int   s  = __ldg(&g_esrc[e]);
                float nm = __ldg(&g_enorm[e]);
                int2 rr = *(const int2*)(hwin + (size_t)s * 128 + lane * 4);
                float2 x0 = __half22float2(*(__half2*)&rr.x);
                float2 x1 = __half22float2(*(__half2*)&rr.y);
                a0 += x0.x * nm; a1 += x0.y * nm;
                a2 += x1.x * nm; a3 += x1.y * nm;
            }
            int c = lane * 4;
            a0 = fmaxf(a0 + bias[c + 0], 0.f);
            a1 = fmaxf(a1 + bias[c + 1], 0.f);
            a2 = fmaxf(a2 + bias[c + 2], 0.f);
            a3 = fmaxf(a3 + bias[c + 3], 0.f);
        }
        __half2 h0 = __floats2half2_rn(a0, a1);
        __half2 h1 = __floats2half2_rn(a2, a3);
        uint2 pk; pk.x = *(uint32_t*)&h0; pk.y = *(uint32_t*)&h1;
        int c  = lane * 4;
        int ch = c >> 5;
        int lc = c & 31;
        *(uint2*)&As[ch * ACH + lrow * STR + lc] = pk;
    }
    CP_WAIT0();
    __syncthreads();

    // ---- phase 2: GEMM over 4 k-chunks ----
    float acc[2][NF][4];
#pragma unroll
    for (int mf = 0; mf < 2; mf++)
#pragma unroll
        for (int nf = 0; nf < NF; nf++)
#pragma unroll
            for (int i = 0; i < 4; i++) acc[mf][nf][i] = 0.f;

#pragma unroll
    for (int ch = 0; ch < 4; ch++) {
        uint16_t* a_s = As + ch * ACH;
        uint16_t* b_s = Bs + ch * BCH;
#pragma unroll
        for (int ks = 0; ks < 2; ks++) {
            uint32_t ah[2][4];
#pragma unroll
            for (int mf = 0; mf < 2; mf++) {
                int rb = (wm * 32 + mf * 16 + g) * STR + ks * 16 + t * 2;
                int r8 = rb + 8 * STR;
                ah[mf][0] = *(const uint32_t*)&a_s[rb];
                ah[mf][1] = *(const uint32_t*)&a_s[r8];
                ah[mf][2] = *(const uint32_t*)&a_s[rb + 8];
                ah[mf][3] = *(const uint32_t*)&a_s[r8 + 8];
            }
#pragma unroll
            for (int nf = 0; nf < NF; nf++) {
                int bb = (wn * WN + nf * 8 + g) * STR + ks * 16 + t * 2;
                uint32_t bh[2];
                bh[0] = *(const uint32_t*)&b_s[bb];
                bh[1] = *(const uint32_t*)&b_s[bb + 8];
#pragma unroll
                for (int mf = 0; mf < 2; mf++)
                    mma16816(acc[mf][nf], ah[mf], bh);
            }
        }
    }

    // ---- epilogue -> hwout (fp16, no bias) ----
#pragma unroll
    for (int mf = 0; mf < 2; mf++) {
        int row = r0 + wm * 32 + mf * 16 + g;
#pragma unroll
        for (int nf = 0; nf < NF; nf++) {
            int col = wn * WN + nf * 8 + t * 2;
            if (row < nrows) {
                float2 v = { acc[mf][nf][0], acc[mf][nf][1] };
                *(__half2*)(hwout + (size_t)row * NCOL + col) = __float22half2_rn(v);
            }
            if (row + 8 < nrows) {
                float2 v = { acc[mf][nf][2], acc[mf][nf][3] };
                *(__half2*)(hwout + (size_t)(row + 8) * NCOL + col) = __float22half2_rn(v);
            }
        }
    }
}

// ---------------- final CSR aggregation (64 cols, fp32 out) -----------------
__global__ void aggregate64_kernel(const __half* __restrict__ hw16,
                                   const float* __restrict__ bias,
                                   float* __restrict__ outf, int n)
{
    constexpr int HD = 64;
    int gw = (blockIdx.x * blockDim.x + threadIdx.x) >> 5;
    if (gw >= n) return;
    int lane = threadIdx.x & 31;

    float acc0, acc1;
    float di = g_dinv[gw];
    float sl = di * di;
    {
        int raw = *(const int*)(hw16 + (size_t)gw * HD + lane * 2);
        float2 f0 = __half22float2(*(__half2*)&raw);
        acc0 = f0.x * sl; acc1 = f0.y * sl;
    }

    int e   = g_rowoff[gw];
    int end = g_rowoff[gw + 1];

    for (; e + 8 <= end; e += 8) {
        int   s[8];
        float nm[8];
#pragma unroll
        for (int j = 0; j < 8; j++) {
            s[j]  = __ldg(&g_esrc[e + j]);
            nm[j] = __ldg(&g_enorm[e + j]);
        }
        int r[8];
#pragma unroll
        for (int j = 0; j < 8; j++)
            r[j] = *(const int*)(hw16 + (size_t)s[j] * HD + lane * 2);
#pragma unroll
        for (int j = 0; j < 8; j++) {
            float2 a = __half22float2(*(__half2*)&r[j]);
            acc0 += a.x * nm[j]; acc1 += a.y * nm[j];
        }
    }
    for (; e < end; e++) {
        int   s  = __ldg(&g_esrc[e]);
        float nm = __ldg(&g_enorm[e]);
        int raw = *(const int*)(hw16 + (size_t)s * HD + lane * 2);
        float2 f0 = __half22float2(*(__half2*)&raw);
        acc0 += f0.x * nm; acc1 += f0.y * nm;
    }

    float2 o;
    o.x = acc0 + bias[lane * 2 + 0];
    o.y = acc1 + bias[lane * 2 + 1];
    *(float2*)(outf + (size_t)gw * HD + lane * 2) = o;
}

// ---------------- launch ----------------------------------------------------
extern "C" void kernel_launch(void* const* d_in, const int* in_sizes, int n_in,
                              void* d_out, int out_size)
{
    const float* x  = (const float*)d_in[0];
    const int*   ei = (const int*)  d_in[1];
    const float* Wu = (const float*)d_in[2];
    const float* bu = (const float*)d_in[3];
    const float* Wb = (const float*)d_in[4];
    const float* bb = (const float*)d_in[5];
    const float* W1 = (const float*)d_in[6];
    const float* b1 = (const float*)d_in[7];
    const float* W2 = (const float*)d_in[8];
    const float* b2 = (const float*)d_in[9];
    const float* W3 = (const float*)d_in[10];
    const float* b3 = (const float*)d_in[11];

    const int N = in_sizes[0] / FEAT;     // 101024
    const int E = in_sizes[1] / 2;        // 2000000
    const int userRows = 1024;

    __half *h16_ptr, *hwa_ptr, *hwb_ptr;
    cudaGetSymbolAddress((void**)&h16_ptr, g_h16);
    cudaGetSymbolAddress((void**)&hwa_ptr, g_hw16a);
    cudaGetSymbolAddress((void**)&hwb_ptr, g_hw16b);

    __half *bh_u, *bh_b, *bh_1, *bh_2, *bh_3;
    cudaGetSymbolAddress((void**)&bh_u, g_bh_u);
    cudaGetSymbolAddress((void**)&bh_b, g_bh_b);
    cudaGetSymbolAddress((void**)&bh_1, g_bh_1);
    cudaGetSymbolAddress((void**)&bh_2, g_bh_2);
    cudaGetSymbolAddress((void**)&bh_3, g_bh_3);

    const int* src = ei;
    const int* dst = ei + E;

    // dynamic smem opt-in
    constexpr int SMEM_P   = (2 * 128 * 40 + 2 * 128 * 40) * 2;   // 40960 B
    constexpr int SMEM_L1  = SMEM_P;                              // 40960 B
    constexpr int SMEM_F128 = (4 * 128 * 40 + 4 * 128 * 40) * 2;  // 81920 B
    constexpr int SMEM_F64  = (4 * 128 * 40 + 4 * 64  * 40) * 2;  // 61440 B
    cudaFuncSetAttribute((const void*)gemm_proj_kernel,         cudaFuncAttributeMaxDynamicSharedMemorySize, SMEM_P);
    cudaFuncSetAttribute((const void*)gemm_h16_kernel,          cudaFuncAttributeMaxDynamicSharedMemorySize, SMEM_L1);
    cudaFuncSetAttribute((const void*)fused_agg_gemm_kernel<128>, cudaFuncAttributeMaxDynamicSharedMemorySize, SMEM_F128);
    cudaFuncSetAttribute((const void*)fused_agg_gemm_kernel<64>,  cudaFuncAttributeMaxDynamicSharedMemorySize, SMEM_F64);

    // one-time side-stream/event setup (host resources; identical work per call)
    static cudaStream_t s2 = 0;
    static cudaEvent_t evFork = 0, evJoin = 0;
    static int sinit = 0;
    if (!sinit) {
        sinit = 1;
        if (cudaStreamCreateWithFlags(&s2, cudaStreamNonBlocking) != cudaSuccess) s2 = 0;
        if (s2) {
            if (cudaEventCreateWithFlags(&evFork, cudaEventDisableTiming) != cudaSuccess ||
                cudaEventCreateWithFlags(&evJoin, cudaEventDisableTiming) != cudaSuccess)
                s2 = 0;
        }
    }
    const bool fork = (s2 != 0);
    cudaStream_t sc = fork ? s2 : 0;

    if (fork) {
        cudaEventRecord(evFork, 0);
        cudaStreamWaitEvent(s2, evFork, 0);
    }

    // 1) degree / CSR build (side stream — overlaps convw + proj + gemm1)
    zero_cnt_kernel<<<(N + 255) / 256, 256, 0, sc>>>(N);
    count_kernel<<<(E + 255) / 256, 256, 0, sc>>>(dst, E);
    dinv_kernel<<<(N + 255) / 256, 256, 0, sc>>>(N);
    int nb = (N + 1023) / 1024;
    scan_block_kernel<<<nb, 1024, 0, sc>>>(N);
    scan_bsum_kernel<<<1, 128, 0, sc>>>(nb, N);
    scan_add_kernel<<<(N + 255) / 256, 256, 0, sc>>>(N);
    fill_kernel<<<(E + 255) / 256, 256, 0, sc>>>(src, dst, E);
    if (fork) cudaEventRecord(evJoin, s2);

    // 2) fused weight conversion — main stream
    convw_all_kernel<<<(303104 + 255) / 256, 256>>>(Wu, Wb, W1, W2, W3,
                                                    bh_u, bh_b, bh_1, bh_2, bh_3);

    int gemmBlocks = (N + 127) / 128;
    int aggBlocks  = (N + 7) / 8;

    // 3) projection: h16 = fp16( x @ (Wu|Wb) + (bu|bb) )
    gemm_proj_kernel<<<gemmBlocks, 256, SMEM_P>>>(
        x, bh_u, bh_b, bu, bb, h16_ptr, N, FEAT, userRows);

    // 4) layer-1 GEMM: hw_a = h16 @ W1
    gemm_h16_kernel<<<gemmBlocks, 256, SMEM_L1>>>(
        h16_ptr, bh_1, hwa_ptr, N, H0);

    if (fork) cudaStreamWaitEvent(0, evJoin, 0);   // CSR ready before first aggregate

    // 5) fused: h = relu(agg(hw_a)+b1); hw_b = h @ W2
    fused_agg_gemm_kernel<128><<<gemmBlocks, 256, SMEM_F128>>>(
        hwa_ptr, b1, bh_2, hwb_ptr, N);

    // 6) fused: h = relu(agg(hw_b)+b2); hw_a = h @ W3 (64 cols)
    fused_agg_gemm_kernel<64><<<gemmBlocks, 256, SMEM_F64>>>(
        hwb_ptr, b2, bh_3, hwa_ptr, N);

    // 7) final aggregate (64 cols, +b3, no relu) -> d_out fp32
    aggregate64_kernel<<<aggBlocks, 256>>>(hwa_ptr, b3, (float*)d_out, N);
}